// round 17
// baseline (speedup 1.0000x reference)
#include <cuda_runtime.h>
#include <cstdint>

#define UNITS   2048
#define IN_DIM  512
#define TSTEPS  8192
#define NCTA    128
#define SCAN_THREADS 256
#define NCTR    16          // counters, one 128B line each
#define CTR_STRIDE 32       // 32 uints = 128B

// 64 MB staging buffer for xin = x @ wax^T + ba
__device__ float g_xin[(size_t)TSTEPS * UNITS];
// 16 counting barriers on distinct L2 lines: CTA i bumps counter i&15.
// Step t complete <=> every counter >= 8*t.
__device__ unsigned g_ctrs[NCTR * CTR_STRIDE];

__device__ __forceinline__ unsigned ld_relaxed_gpu(const unsigned* p) {
    unsigned v;
    asm volatile("ld.relaxed.gpu.u32 %0, [%1];" : "=r"(v) : "l"(p) : "memory");
    return v;
}
__device__ __forceinline__ void red_release_add(unsigned* p, unsigned v) {
    asm volatile("red.release.gpu.global.add.u32 [%0], %1;"
                 :: "l"(p), "r"(v) : "memory");
}
__device__ __forceinline__ unsigned long long ffma2(
    unsigned long long a, unsigned long long b, unsigned long long c) {
    unsigned long long d;
    asm("fma.rn.f32x2 %0, %1, %2, %3;" : "=l"(d) : "l"(a), "l"(b), "l"(c));
    return d;
}
__device__ __forceinline__ unsigned long long packf2(float x, float y) {
    unsigned long long p;
    asm("mov.b64 %0, {%1, %2};" : "=l"(p) : "f"(x), "f"(y));
    return p;
}
__device__ __forceinline__ float pair_sum(unsigned long long p) {
    float lo, hi;
    asm("mov.b64 {%0, %1}, %2;" : "=f"(lo), "=f"(hi) : "l"(p));
    return lo + hi;
}

// ---------------------------------------------------------------------------
// Phase 1: xin[t][u] = sum_d x[t][d] * wax[u][d] + ba[u]
// block (0,0) also resets the scan barrier counters (every replay).
// ---------------------------------------------------------------------------
__global__ __launch_bounds__(256) void xin_gemm_kernel(
    const float* __restrict__ x,     // [8192][512]
    const float* __restrict__ wax,   // [2048][512]
    const float* __restrict__ ba)    // [2048]
{
    if (blockIdx.x == 0 && blockIdx.y == 0) {
        for (int i = threadIdx.x; i < NCTR * CTR_STRIDE; i += 256)
            g_ctrs[i] = 0u;
    }

    __shared__ float As[16][128 + 4];
    __shared__ float Bs[16][64 + 4];

    const int tid = threadIdx.x;
    const int bm = blockIdx.y * 128;
    const int bn = blockIdx.x * 64;
    const int tx = tid & 15;
    const int ty = tid >> 4;

    float acc[8][4];
#pragma unroll
    for (int i = 0; i < 8; i++)
#pragma unroll
        for (int j = 0; j < 4; j++) acc[i][j] = 0.f;

    const int lr = tid >> 2;
    const int lc = (tid & 3) * 4;

    for (int k0 = 0; k0 < IN_DIM; k0 += 16) {
        float4 a0 = *(const float4*)&x[(size_t)(bm + lr) * IN_DIM + k0 + lc];
        float4 a1 = *(const float4*)&x[(size_t)(bm + lr + 64) * IN_DIM + k0 + lc];
        float4 b0 = *(const float4*)&wax[(size_t)(bn + lr) * IN_DIM + k0 + lc];

        As[lc + 0][lr] = a0.x; As[lc + 1][lr] = a0.y;
        As[lc + 2][lr] = a0.z; As[lc + 3][lr] = a0.w;
        As[lc + 0][lr + 64] = a1.x; As[lc + 1][lr + 64] = a1.y;
        As[lc + 2][lr + 64] = a1.z; As[lc + 3][lr + 64] = a1.w;
        Bs[lc + 0][lr] = b0.x; Bs[lc + 1][lr] = b0.y;
        Bs[lc + 2][lr] = b0.z; Bs[lc + 3][lr] = b0.w;
        __syncthreads();

#pragma unroll
        for (int kk = 0; kk < 16; kk++) {
            float4 av0 = *(const float4*)&As[kk][ty * 8];
            float4 av1 = *(const float4*)&As[kk][ty * 8 + 4];
            float4 bv  = *(const float4*)&Bs[kk][tx * 4];
            float a[8] = {av0.x, av0.y, av0.z, av0.w, av1.x, av1.y, av1.z, av1.w};
            float b[4] = {bv.x, bv.y, bv.z, bv.w};
#pragma unroll
            for (int i = 0; i < 8; i++)
#pragma unroll
                for (int j = 0; j < 4; j++)
                    acc[i][j] = fmaf(a[i], b[j], acc[i][j]);
        }
        __syncthreads();
    }

    float4 bav = *(const float4*)&ba[bn + tx * 4];
#pragma unroll
    for (int i = 0; i < 8; i++) {
        float4 c;
        c.x = acc[i][0] + bav.x;
        c.y = acc[i][1] + bav.y;
        c.z = acc[i][2] + bav.z;
        c.w = acc[i][3] + bav.w;
        *(float4*)&g_xin[(size_t)(bm + ty * 8 + i) * UNITS + bn + tx * 4] = c;
    }
}

// ---------------------------------------------------------------------------
// Phase 2: persistent scan — column-split matvec, role-split warps.
// 128 CTAs x 256 threads; CTA owns 16 output rows urow0=16*cta..+15.
// Warp w owns columns [w*256,(w+1)*256); lane owns 8 cols for ALL 16 rows
// (64 f32x2 weight pairs in regs). State read ONCE per CTA (1MB/step).
// Per step t>0:
//   warp0 (POLLER): polls g_ctrs[(lane&15)*32] (one 16-line load instr)
//   until __all_sync(v >= 8t); no fence (R11-validated).
//   -> BAR_A (gates state freshness AND red_sm reuse)
//   -> all warps: 2 LDG.128 state, 16 rows x 4 FFMA2, value-halving fold
//   (constant-index selects -> SEL, no spills), even lanes -> red_sm
//   -> BAR_B
//   -> warp7 (FINALIZER): lanes 0-15 sum 8 partials + xin, tanh, ONE
//   predicated STG of out[t], then lane0 red.release.add — while warp0 has
//   ALREADY looped and is polling for t+1 (finalize tail hidden; poll
//   can't pass until our own release, so this is self-synchronizing).
//   No BAR_C: store->RED are program-ordered in warp7; red_sm(t) is read
//   by warp7 before it reaches BAR_A(t+1).
// ---------------------------------------------------------------------------
__global__ __launch_bounds__(SCAN_THREADS, 1) void scan_kernel(
    const float* __restrict__ waa,   // [2048][2048]
    float* __restrict__ out)         // [8192][2048]
{
    __shared__ float red_sm[8][16];

    const int tid  = threadIdx.x;
    const int lane = tid & 31;
    const int warp = tid >> 5;               // 0..7
    const int cta  = blockIdx.x;             // 0..127
    const int urow0 = cta * 16;
    const int col0  = warp * 256 + lane * 8; // this lane's 8 columns

    // Preload weights: wp[r][p] = waa[urow0+r][col0+2p .. +2p+1] packed
    unsigned long long wp[16][4];
#pragma unroll
    for (int r = 0; r < 16; r++) {
        const float* wr = &waa[(size_t)(urow0 + r) * UNITS + col0];
        float4 fa = *(const float4*)(wr);
        float4 fb = *(const float4*)(wr + 4);
        wp[r][0] = packf2(fa.x, fa.y);
        wp[r][1] = packf2(fa.z, fa.w);
        wp[r][2] = packf2(fb.x, fb.y);
        wp[r][3] = packf2(fb.z, fb.w);
    }

    // this lane's output row after the fold (bit pattern of the selects)
    const int myrow = ((lane & 16) ? 8 : 0) | ((lane & 8) ? 4 : 0) |
                      ((lane & 4) ? 2 : 0) | ((lane & 2) ? 1 : 0);

    const unsigned* poll_addr = &g_ctrs[(lane & 15) * CTR_STRIDE];
    unsigned* my_ctr = &g_ctrs[(cta & 15) * CTR_STRIDE];

    for (int t = 0; t < TSTEPS; t++) {
        // finalizer warp prefetches xin (independent of the wait)
        float xv = 0.f;
        if (warp == 7 && lane < 16)
            xv = __ldg(&g_xin[(size_t)t * UNITS + urow0 + lane]);

        if (t > 0) {
            if (warp == 0) {
                const unsigned target = (unsigned)t * 8u;  // 8 CTAs per counter
                for (;;) {
                    unsigned v = ld_relaxed_gpu(poll_addr);
                    if (__all_sync(0xffffffffu, v >= target)) break;
                }
            }
            __syncthreads();   // BAR_A: state fresh + red_sm reusable

            // lane's 8 state values: 2 x LDG.128 (state read ONCE per CTA)
            const float* ab = out + (size_t)(t - 1) * UNITS + col0;
            float4 av0 = *(const float4*)(ab);
            float4 av1 = *(const float4*)(ab + 4);
            unsigned long long pa0 = packf2(av0.x, av0.y);
            unsigned long long pa1 = packf2(av0.z, av0.w);
            unsigned long long pa2 = packf2(av1.x, av1.y);
            unsigned long long pa3 = packf2(av1.z, av1.w);

            // 16 rows x 4 chained FFMA2 (rows independent -> ILP=16)
            float v[16];
#pragma unroll
            for (int r = 0; r < 16; r++) {
                unsigned long long s = ffma2(wp[r][0], pa0, 0ull);
                s = ffma2(wp[r][1], pa1, s);
                s = ffma2(wp[r][2], pa2, s);
                s = ffma2(wp[r][3], pa3, s);
                v[r] = pair_sum(s);
            }

            // value-halving fold; all selects use CONSTANT indices (SEL)
#pragma unroll
            for (int i = 0; i < 16; i++)
                v[i] += __shfl_xor_sync(0xffffffffu, v[i], 16);
            float u8[8];
#pragma unroll
            for (int i = 0; i < 8; i++)
                u8[i] = (lane & 16) ? v[i + 8] : v[i];
#pragma unroll
            for (int i = 0; i < 8; i++)
                u8[i] += __shfl_xor_sync(0xffffffffu, u8[i], 8);
            float u4[4];
#pragma unroll
            for (int i = 0; i < 4; i++)
                u4[i] = (lane & 8) ? u8[i + 4] : u8[i];
#pragma unroll
            for (int i = 0; i < 4; i++)
                u4[i] += __shfl_xor_sync(0xffffffffu, u4[i], 4);
            float u2[2];
            u2[0] = (lane & 4) ? u4[2] : u4[0];
            u2[1] = (lane & 4) ? u4[3] : u4[1];
            u2[0] += __shfl_xor_sync(0xffffffffu, u2[0], 2);
            u2[1] += __shfl_xor_sync(0xffffffffu, u2[1], 2);
            float y = (lane & 2) ? u2[1] : u2[0];
            y += __shfl_xor_sync(0xffffffffu, y, 1);

            if (!(lane & 1)) red_sm[warp][myrow] = y;
        } else {
            if (!(lane & 1)) red_sm[warp][myrow] = 0.f;
        }
        __syncthreads();   // BAR_B: red_sm ready

        // FINALIZER (warp7): final reduce + tanh + store + release.
        // warp0 has already looped to the top and is polling for t+1.
        if (warp == 7) {
            if (lane < 16) {
                float s = xv;
#pragma unroll
                for (int w = 0; w < 8; w++) s += red_sm[w][lane];
                out[(size_t)t * UNITS + urow0 + lane] = tanhf(s);
            }
            // ONE predicated STG above precedes this RED in warp program
            // order (both volatile) — no barrier needed.
            if (lane == 0)
                red_release_add(my_ctr, 1u);
        }
    }
}

// ---------------------------------------------------------------------------
extern "C" void kernel_launch(void* const* d_in, const int* in_sizes, int n_in,
                              void* d_out, int out_size) {
    const float* x   = (const float*)d_in[0];   // (1, 8192, 512)
    const float* waa = (const float*)d_in[1];   // (2048, 2048)
    const float* wax = (const float*)d_in[2];   // (2048, 512)
    const float* ba  = (const float*)d_in[3];   // (2048, 1)
    float* out = (float*)d_out;                 // (1, 8192, 2048)

    dim3 grid(UNITS / 64, TSTEPS / 128);        // (32, 64)
    xin_gemm_kernel<<<grid, 256>>>(x, wax, ba); // also resets g_ctrs

    scan_kernel<<<NCTA, SCAN_THREADS>>>(waa, out);
}